// round 15
// baseline (speedup 1.0000x reference)
#include <cuda_runtime.h>
#include <cuda_bf16.h>

#define BB      32
#define SS      64
#define DD      8
#define NEIDX   512
#define EMAX    150000
#define NW      4       // warps per CTA in fused kernel (128 threads)
#define NBC     128     // binning CTAs

typedef unsigned long long u64;

__device__ __forceinline__ u64 fma2(u64 a, u64 b, u64 c) {
    u64 d;
    asm("fma.rn.f32x2 %0, %1, %2, %3;" : "=l"(d) : "l"(a), "l"(b), "l"(c));
    return d;
}
__device__ __forceinline__ u64 pack2(float lo, float hi) {
    u64 d;
    asm("mov.b64 %0, {%1, %2};" : "=l"(d) : "f"(lo), "f"(hi));
    return d;
}
__device__ __forceinline__ float hsum2(u64 v) {
    float lo, hi;
    asm("mov.b64 {%0, %1}, %2;" : "=f"(lo), "=f"(hi) : "l"(v));
    return lo + hi;
}

// ---------------- device scratch ----------------
__device__ int   g_part[NBC][NEIDX];
__device__ int   g_base[NBC][NEIDX];
__device__ int   g_bin_start[NEIDX + 1];
__device__ int   g_sorted[EMAX];           // packed: c0 | (c1<<5)
__device__ float g_psum[2][NEIDX][BB * 32];
__device__ int   g_pcnt[2][NEIDX][BB];

// ---------------- K1: per-CTA histogram ----------------
__global__ __launch_bounds__(512) void k_hist(const int4* __restrict__ inc, int E) {
    __shared__ int sh[NEIDX];
    int tid = threadIdx.x;
    sh[tid] = 0;
    __syncthreads();
    int per = (E + NBC - 1) / NBC;
    int beg = blockIdx.x * per;
    int end = min(beg + per, E);
    for (int i = beg + tid; i < end; i += 512) {
        int4 r = inc[i];
        atomicAdd(&sh[r.z * DD + r.w], 1);
    }
    __syncthreads();
    g_part[blockIdx.x][tid] = sh[tid];
}

// ---------------- K2: scan ----------------
__global__ __launch_bounds__(NEIDX) void k_scan() {
    __shared__ int s[NEIDX];
    int t = threadIdx.x;
    int run = 0;
    #pragma unroll 8
    for (int c = 0; c < NBC; c++) {
        int v = g_part[c][t];
        g_base[c][t] = run;
        run += v;
    }
    s[t] = run;
    __syncthreads();
    for (int off = 1; off < NEIDX; off <<= 1) {
        int x = (t >= off) ? s[t - off] : 0;
        __syncthreads();
        s[t] += x;
        __syncthreads();
    }
    g_bin_start[t + 1] = s[t];
    if (t == 0) g_bin_start[0] = 0;
}

// ---------------- K3: scatter ----------------
__global__ __launch_bounds__(512) void k_scatter(const int4* __restrict__ inc, int E) {
    __shared__ int sc[NEIDX];
    int tid = threadIdx.x;
    sc[tid] = g_bin_start[tid] + g_base[blockIdx.x][tid];
    __syncthreads();
    int per = (E + NBC - 1) / NBC;
    int beg = blockIdx.x * per;
    int end = min(beg + per, E);
    for (int i = beg + tid; i < end; i += 512) {
        int4 r = inc[i];
        int b = r.z * DD + r.w;
        int pos = atomicAdd(&sc[b], 1);
        g_sorted[pos] = r.x | (r.y << 5);
    }
}

// ---------------- K4: edge MLP + partial segment sums ----------------
// Grid = 1024: CTA (e, half) processes half of bin e's edges. Edge-per-lane,
// FFMA2, conflict-free staged reduce. Partial sums/counts go to g_psum/g_pcnt
// with plain stores (halves disjoint). Register-dieted (H packed in layer 1,
// no prefetch) + launch_bounds(128,6) -> ~6 CTAs/SM resident.
__global__ __launch_bounds__(NW * 32, 6) void k_fused(
    const float* __restrict__ nodes,
    const float* __restrict__ W0,  const float* __restrict__ b0,
    const float* __restrict__ W1,  const float* __restrict__ b1)
{
    __shared__ __align__(16) float sW0[512];        // in_core0 [o][i] 32x16
    __shared__ __align__(16) float sW1[1024];       // in_core1 [o][i] 32x32
    __shared__ __align__(16) float s_stage[NW * 33 * 32];
    __shared__ __align__(16) float s_acc[BB * 32];  // [c0][o]
    __shared__ int   s_cnt[BB];
    __shared__ float sb0[32], sb1[32];

    int e    = blockIdx.x >> 1;
    int half = blockIdx.x & 1;
    int tid  = threadIdx.x;
    int lane = tid & 31;
    int warp = tid >> 5;
    int c2   = e >> 3;

    for (int t = tid; t < 512;  t += NW * 32) sW0[t] = W0[e * 512 + t];
    for (int t = tid; t < 1024; t += NW * 32) sW1[t] = W1[e * 1024 + t];
    if (tid < 32) { sb0[tid] = b0[e * 32 + tid]; sb1[tid] = b1[e * 32 + tid]; }
    if (tid < BB) s_cnt[tid] = 0;
    for (int t = tid; t < BB * 32; t += NW * 32) s_acc[t] = 0.f;
    __syncthreads();

    int bs    = g_bin_start[e];
    int n     = g_bin_start[e + 1] - bs;
    int hbeg  = bs + (n * half) / 2;
    int hend  = bs + (n * (half + 1)) / 2;
    float* ST = s_stage + warp * 33 * 32;

    float racc = 0.f;
    int   rcur = -1;

    for (int j0 = hbeg + warp * 32; j0 < hend; j0 += NW * 32) {
        int j = j0 + lane;
        bool v = (j < hend);
        int pk = v ? g_sorted[j] : -1;
        int c1 = (pk >> 5) & 1023;

        const ulonglong2* xp = (const ulonglong2*)(nodes + (v ? (c1 * SS + c2) * 16 : 0));
        ulonglong2 xa = xp[0], xb = xp[1], xc = xp[2], xd = xp[3];
        u64 X[8] = {xa.x, xa.y, xb.x, xb.y, xc.x, xc.y, xd.x, xd.y};

        // layer 1 with pack-as-you-go: only H[16] stays live
        u64 H[16];
        #pragma unroll
        for (int p = 0; p < 16; p++) {
            const ulonglong2* w0p = (const ulonglong2*)(sW0 + (2 * p) * 16);
            const ulonglong2* w1p = (const ulonglong2*)(sW0 + (2 * p + 1) * 16);
            ulonglong2 wa0 = w0p[0], wb0 = w0p[1], wc0 = w0p[2], wd0 = w0p[3];
            ulonglong2 wa1 = w1p[0], wb1 = w1p[1], wc1 = w1p[2], wd1 = w1p[3];
            u64 a0 = fma2(wa0.x, X[0], 0ULL);
            u64 a1 = fma2(wa1.x, X[0], 0ULL);
            a0 = fma2(wa0.y, X[1], a0); a1 = fma2(wa1.y, X[1], a1);
            a0 = fma2(wb0.x, X[2], a0); a1 = fma2(wb1.x, X[2], a1);
            a0 = fma2(wb0.y, X[3], a0); a1 = fma2(wb1.y, X[3], a1);
            a0 = fma2(wc0.x, X[4], a0); a1 = fma2(wc1.x, X[4], a1);
            a0 = fma2(wc0.y, X[5], a0); a1 = fma2(wc1.y, X[5], a1);
            a0 = fma2(wd0.x, X[6], a0); a1 = fma2(wd1.x, X[6], a1);
            a0 = fma2(wd0.y, X[7], a0); a1 = fma2(wd1.y, X[7], a1);
            float f0 = fmaxf(hsum2(a0) + sb0[2 * p],     0.f);
            float f1 = fmaxf(hsum2(a1) + sb0[2 * p + 1], 0.f);
            H[p] = pack2(f0, f1);
        }

        // layer 2 -> stage relu(g) at stride 33 (conflict-free)
        #pragma unroll 8
        for (int o = 0; o < 32; o++) {
            const ulonglong2* w = (const ulonglong2*)(sW1 + o * 32);
            u64 a = 0ULL;
            #pragma unroll
            for (int q = 0; q < 8; q++) {
                ulonglong2 ww = w[q];
                a = fma2(ww.x, H[2 * q],     a);
                a = fma2(ww.y, H[2 * q + 1], a);
            }
            ST[lane * 33 + o] = fmaxf(hsum2(a) + sb1[o], 0.f);
        }
        if (pk >= 0) atomicAdd(&s_cnt[pk & 31], 1);
        __syncwarp();

        // transposed reduce: lane = o; flush ATOMS at bank=lane (conflict-free)
        #pragma unroll
        for (int j2 = 0; j2 < 32; j2++) {
            int pk2 = __shfl_sync(0xffffffffu, pk, j2);
            if (pk2 >= 0) {
                int c02 = pk2 & 31;
                if (c02 != rcur) {
                    if (rcur >= 0) atomicAdd(&s_acc[rcur * 32 + lane], racc);
                    racc = 0.f;
                    rcur = c02;
                }
                racc += ST[j2 * 33 + lane];
            }
        }
        __syncwarp();
    }
    if (rcur >= 0) atomicAdd(&s_acc[rcur * 32 + lane], racc);
    __syncthreads();

    // ---- write partials (plain stores; halves disjoint) ----
    for (int t = tid; t < BB * 32; t += NW * 32) g_psum[half][e][t] = s_acc[t];
    if (tid < BB) g_pcnt[half][e][tid] = s_cnt[tid];
}

// ---------------- K5: combine halves + mean + output MLP ----------------
__global__ __launch_bounds__(128) void k_epi(
    const float* __restrict__ oW0, const float* __restrict__ ob0,
    const float* __restrict__ oW1, const float* __restrict__ ob1,
    float* __restrict__ out)
{
    __shared__ __align__(16) float s_w0t[1024];   // out_core0 transposed [i][o]
    __shared__ __align__(16) float s_w1t[512];    // out_core1 transposed [i][o]
    __shared__ __align__(16) float s_ef[BB * 32];
    __shared__ __align__(16) float s_hh[BB * 32];
    __shared__ int   s_cnt[BB];
    __shared__ float s_ob0[32], s_ob1[16];

    int e   = blockIdx.x;
    int tid = threadIdx.x;

    for (int t = tid; t < 1024; t += 128) {
        int o = t >> 5, i = t & 31;
        s_w0t[i * 32 + o] = oW0[e * 1024 + t];
    }
    for (int t = tid; t < 512; t += 128) {
        int o = t >> 5, i = t & 31;
        s_w1t[i * 16 + o] = oW1[e * 512 + t];
    }
    if (tid < 32) s_ob0[tid] = ob0[e * 32 + tid];
    if (tid < 16) s_ob1[tid] = ob1[e * 16 + tid];
    if (tid < BB) s_cnt[tid] = g_pcnt[0][e][tid] + g_pcnt[1][e][tid];
    __syncthreads();

    for (int t = tid; t < BB * 32; t += 128) {
        int bl = t >> 5;
        int c = s_cnt[bl];
        float s = g_psum[0][e][t] + g_psum[1][e][t];
        s_ef[t] = (c > 0) ? s / (float)c : 0.f;
    }
    __syncthreads();

    for (int t = tid; t < BB * 32; t += 128) {
        int bl = t >> 5, o = t & 31;
        float s = s_ob0[o];
        #pragma unroll
        for (int i = 0; i < 32; i++)
            s = fmaf(s_w0t[i * 32 + o], s_ef[bl * 32 + i], s);
        s_hh[t] = fmaxf(s, 0.f);
    }
    __syncthreads();

    for (int t = tid; t < BB * 16; t += 128) {
        int bl = t >> 4, o = t & 15;
        float s = s_ob1[o];
        #pragma unroll
        for (int i = 0; i < 32; i++)
            s = fmaf(s_w1t[i * 16 + o], s_hh[bl * 32 + i], s);
        out[(bl * NEIDX + e) * 16 + o] = fmaxf(s, 0.f);
    }
}

// ---------------- launch ----------------
extern "C" void kernel_launch(void* const* d_in, const int* in_sizes, int n_in,
                              void* d_out, int out_size) {
    const float* nodes = (const float*)d_in[0];
    const float* ic0   = (const float*)d_in[1];
    const float* ib0   = (const float*)d_in[2];
    const float* ic1   = (const float*)d_in[3];
    const float* ib1   = (const float*)d_in[4];
    const float* oc0   = (const float*)d_in[5];
    const float* ob0   = (const float*)d_in[6];
    const float* oc1   = (const float*)d_in[7];
    const float* ob1   = (const float*)d_in[8];
    const int4*  inc   = (const int4*)d_in[9];
    int E = in_sizes[9] / 4;
    float* out = (float*)d_out;

    k_hist<<<NBC, 512>>>(inc, E);
    k_scan<<<1, NEIDX>>>();
    k_scatter<<<NBC, 512>>>(inc, E);
    k_fused<<<NEIDX * 2, NW * 32>>>(nodes, ic0, ib0, ic1, ib1);
    k_epi<<<NEIDX, 128>>>(oc0, ob0, oc1, ob1, out);
}

// round 16
// speedup vs baseline: 1.6974x; 1.6974x over previous
#include <cuda_runtime.h>
#include <cuda_bf16.h>

#define BB      32
#define SS      64
#define DD      8
#define NEIDX   512
#define CAP     512     // slots per bin (mean 293, +12 sigma safe)
#define EMAX    150000
#define NW      4       // warps per CTA in fused kernel (128 threads)
#define NBC     128     // binning CTAs

typedef unsigned long long u64;

__device__ __forceinline__ u64 fma2(u64 a, u64 b, u64 c) {
    u64 d;
    asm("fma.rn.f32x2 %0, %1, %2, %3;" : "=l"(d) : "l"(a), "l"(b), "l"(c));
    return d;
}
__device__ __forceinline__ u64 pack2(float lo, float hi) {
    u64 d;
    asm("mov.b64 %0, {%1, %2};" : "=l"(d) : "f"(lo), "f"(hi));
    return d;
}
__device__ __forceinline__ float hsum2(u64 v) {
    float lo, hi;
    asm("mov.b64 {%0, %1}, %2;" : "=f"(lo), "=f"(hi) : "l"(v));
    return lo + hi;
}

// ---------------- device scratch ----------------
__device__ int g_cnt[NEIDX];
__device__ int g_slot[NEIDX * CAP];     // packed: c0 | (c1<<5), per-bin slots

// ---------------- K0: zero bin counters ----------------
__global__ void k_zero() {
    g_cnt[threadIdx.x] = 0;
}

// ---------------- K1: combined hist + reserve + scatter (single pass) ------
__global__ __launch_bounds__(512) void k_bin(const int4* __restrict__ inc, int E) {
    __shared__ int sh[NEIDX];   // CTA-local histogram
    __shared__ int sc[NEIDX];   // per-bin running cursor (within reserved range)
    int tid = threadIdx.x;
    sh[tid] = 0;
    __syncthreads();
    int per = (E + NBC - 1) / NBC;
    int beg = blockIdx.x * per;
    int end = min(beg + per, E);
    for (int i = beg + tid; i < end; i += 512) {
        int4 r = inc[i];
        atomicAdd(&sh[r.z * DD + r.w], 1);
    }
    __syncthreads();
    int c = sh[tid];
    sc[tid] = c ? atomicAdd(&g_cnt[tid], c) : 0;    // reserve range in bin
    __syncthreads();
    for (int i = beg + tid; i < end; i += 512) {
        int4 r = inc[i];
        int b = r.z * DD + r.w;
        int pos = atomicAdd(&sc[b], 1);             // SMEM cursor
        if (pos < CAP) g_slot[b * CAP + pos] = r.x | (r.y << 5);
    }
}

// ---------------- K2: fused edge MLP + segment mean + output MLP ----------------
// R13 kernel (best measured): one CTA per eidx, NW=4, edge-per-lane with 32
// independent gathers in flight, FFMA2 compute, conflict-free staged reduce.
__global__ __launch_bounds__(NW * 32, 4) void k_fused(
    const float* __restrict__ nodes,
    const float* __restrict__ W0,  const float* __restrict__ b0,
    const float* __restrict__ W1,  const float* __restrict__ b1,
    const float* __restrict__ oW0, const float* __restrict__ ob0,
    const float* __restrict__ oW1, const float* __restrict__ ob1,
    float* __restrict__ out)
{
    __shared__ __align__(16) float sW0[512];        // in_core0 [o][i] 32x16; reused as w1t
    __shared__ __align__(16) float sW1[1024];       // in_core1 [o][i] 32x32; reused as w0t
    __shared__ __align__(16) float s_stage[NW * 33 * 32]; // per-warp g staging; reused as ef
    __shared__ __align__(16) float s_acc[BB * 32];  // [c0][o]; reused as hh
    __shared__ int   s_cnt[BB];
    __shared__ float sb0[32], sb1[32], s_ob0[32], s_ob1[16];

    int e    = blockIdx.x;
    int tid  = threadIdx.x;
    int lane = tid & 31;
    int warp = tid >> 5;
    int c2   = e >> 3;

    for (int t = tid; t < 512;  t += NW * 32) sW0[t] = W0[e * 512 + t];
    for (int t = tid; t < 1024; t += NW * 32) sW1[t] = W1[e * 1024 + t];
    if (tid < 32) { sb0[tid] = b0[e * 32 + tid]; sb1[tid] = b1[e * 32 + tid]; }
    if (tid < BB) s_cnt[tid] = 0;
    for (int t = tid; t < BB * 32; t += NW * 32) s_acc[t] = 0.f;
    __syncthreads();

    int n     = min(g_cnt[e], CAP);
    int start = e * CAP;
    int end   = start + n;
    float* ST = s_stage + warp * 33 * 32;

    float racc = 0.f;
    int   rcur = -1;

    for (int j0 = start + warp * 32; j0 < end; j0 += NW * 32) {
        int j = j0 + lane;
        bool v = (j < end);
        int pk = v ? g_slot[j] : -1;
        int c0 = pk & 31;
        int c1 = (pk >> 5) & 1023;

        // 8 packed x-pairs (4x LDG.128, independent across lanes)
        const ulonglong2* xp = (const ulonglong2*)(nodes + (v ? (c1 * SS + c2) * 16 : 0));
        ulonglong2 xa = xp[0], xb = xp[1], xc = xp[2], xd = xp[3];
        u64 X[8] = {xa.x, xa.y, xb.x, xb.y, xc.x, xc.y, xd.x, xd.y};

        // layer 1: packed over i-pairs; weights broadcast from SMEM
        float h[32];
        #pragma unroll
        for (int o = 0; o < 32; o++) {
            const ulonglong2* w = (const ulonglong2*)(sW0 + o * 16);
            ulonglong2 wa = w[0], wb = w[1], wc = w[2], wd = w[3];
            u64 a = fma2(wa.x, X[0], 0ULL);
            a = fma2(wa.y, X[1], a);
            a = fma2(wb.x, X[2], a);
            a = fma2(wb.y, X[3], a);
            a = fma2(wc.x, X[4], a);
            a = fma2(wc.y, X[5], a);
            a = fma2(wd.x, X[6], a);
            a = fma2(wd.y, X[7], a);
            h[o] = fmaxf(hsum2(a) + sb0[o], 0.f);
        }

        u64 H[16];
        #pragma unroll
        for (int i = 0; i < 16; i++) H[i] = pack2(h[2 * i], h[2 * i + 1]);

        // layer 2 -> stage relu(g) at stride 33 (banks (lane+o)%32: conflict-free)
        #pragma unroll 8
        for (int o = 0; o < 32; o++) {
            const ulonglong2* w = (const ulonglong2*)(sW1 + o * 32);
            u64 a = 0ULL;
            #pragma unroll
            for (int q = 0; q < 8; q++) {
                ulonglong2 ww = w[q];
                a = fma2(ww.x, H[2 * q],     a);
                a = fma2(ww.y, H[2 * q + 1], a);
            }
            ST[lane * 33 + o] = fmaxf(hsum2(a) + sb1[o], 0.f);
        }
        if (pk >= 0) atomicAdd(&s_cnt[c0], 1);
        __syncwarp();

        // transposed reduce: lane = o; flush ATOMS at bank=lane (conflict-free)
        #pragma unroll
        for (int j2 = 0; j2 < 32; j2++) {
            int pk2 = __shfl_sync(0xffffffffu, pk, j2);
            if (pk2 >= 0) {
                int c02 = pk2 & 31;
                if (c02 != rcur) {
                    if (rcur >= 0) atomicAdd(&s_acc[rcur * 32 + lane], racc);
                    racc = 0.f;
                    rcur = c02;
                }
                racc += ST[j2 * 33 + lane];
            }
        }
        __syncwarp();
    }
    if (rcur >= 0) atomicAdd(&s_acc[rcur * 32 + lane], racc);
    __syncthreads();

    // ---- epilogue: reuse sW1 -> w0t, sW0 -> w1t, s_stage -> ef ----
    float* s_ef = s_stage;
    for (int t = tid; t < 1024; t += NW * 32) {
        int o = t >> 5, i = t & 31;
        sW1[i * 32 + o] = oW0[e * 1024 + t];     // out_core0 [o][i] -> [i][o]
    }
    for (int t = tid; t < 512; t += NW * 32) {
        int o = t >> 5, i = t & 31;
        sW0[i * 16 + o] = oW1[e * 512 + t];      // out_core1 [o][i] (16x32) -> [i][o]
    }
    if (tid < 32) s_ob0[tid] = ob0[e * 32 + tid];
    if (tid < 16) s_ob1[tid] = ob1[e * 16 + tid];

    // ---- mean ----
    for (int t = tid; t < BB * 32; t += NW * 32) {
        int bl = t >> 5;
        int c = s_cnt[bl];
        s_ef[t] = (c > 0) ? s_acc[t] / (float)c : 0.f;
    }
    __syncthreads();

    // ---- out layer 1 (hh reuses s_acc) ----
    for (int t = tid; t < BB * 32; t += NW * 32) {
        int bl = t >> 5, o = t & 31;
        float s = s_ob0[o];
        #pragma unroll
        for (int i = 0; i < 32; i++)
            s = fmaf(sW1[i * 32 + o], s_ef[bl * 32 + i], s);
        s_acc[t] = fmaxf(s, 0.f);
    }
    __syncthreads();

    // ---- out layer 2 + store ----
    for (int t = tid; t < BB * 16; t += NW * 32) {
        int bl = t >> 4, o = t & 15;
        float s = s_ob1[o];
        #pragma unroll
        for (int i = 0; i < 32; i++)
            s = fmaf(sW0[i * 16 + o], s_acc[bl * 32 + i], s);
        out[(bl * NEIDX + e) * 16 + o] = fmaxf(s, 0.f);
    }
}

// ---------------- launch ----------------
extern "C" void kernel_launch(void* const* d_in, const int* in_sizes, int n_in,
                              void* d_out, int out_size) {
    const float* nodes = (const float*)d_in[0];
    const float* ic0   = (const float*)d_in[1];
    const float* ib0   = (const float*)d_in[2];
    const float* ic1   = (const float*)d_in[3];
    const float* ib1   = (const float*)d_in[4];
    const float* oc0   = (const float*)d_in[5];
    const float* ob0   = (const float*)d_in[6];
    const float* oc1   = (const float*)d_in[7];
    const float* ob1   = (const float*)d_in[8];
    const int4*  inc   = (const int4*)d_in[9];
    int E = in_sizes[9] / 4;
    float* out = (float*)d_out;

    k_zero<<<1, NEIDX>>>();
    k_bin<<<NBC, 512>>>(inc, E);
    k_fused<<<NEIDX, NW * 32>>>(nodes, ic0, ib0, ic1, ib1,
                                oc0, ob0, oc1, ob1, out);
}